// round 4
// baseline (speedup 1.0000x reference)
#include <cuda_runtime.h>

// LSTM B=4096, T=999, I=1, H=51, O=1, future=0.
// Layout: CTA = 1 batch-PAIR (2 batch rows packed into f32x2 lanes).
//   204 threads: tid = 4*j + gate  (gate in {i,f,g,o} PyTorch order, j = hidden unit).
//   Each thread holds its gate row of W_hh in 51 packed (w,w) registers and
//   computes the gate preactivation for BOTH batches with fma.rn.f32x2.
//   h lives in SMEM as f32x2 pairs -> every read is a warp broadcast (free).
//   Gate combine via 4-lane shfl allgather -> ONE __syncthreads per step.
//   x preloaded to SMEM as pairs; y buffered in SMEM, flushed coalesced at end.

#define HID    51
#define HP     52          // padded pair count (pad = 0)
#define SEQLEN 999
#define NTHR   204
#define BATCH  4096

typedef unsigned long long u64;

__device__ __forceinline__ u64 pk2(float lo, float hi) {
    u64 r;
    asm("mov.b64 %0, {%1, %2};"
        : "=l"(r) : "r"(__float_as_uint(lo)), "r"(__float_as_uint(hi)));
    return r;
}
__device__ __forceinline__ void upk2(u64 v, float& lo, float& hi) {
    unsigned a, b;
    asm("mov.b64 {%0, %1}, %2;" : "=r"(a), "=r"(b) : "l"(v));
    lo = __uint_as_float(a); hi = __uint_as_float(b);
}
__device__ __forceinline__ u64 ffma2(u64 a, u64 b, u64 c) {
    u64 d; asm("fma.rn.f32x2 %0, %1, %2, %3;" : "=l"(d) : "l"(a), "l"(b), "l"(c));
    return d;
}
__device__ __forceinline__ u64 fmul2(u64 a, u64 b) {
    u64 d; asm("mul.rn.f32x2 %0, %1, %2;" : "=l"(d) : "l"(a), "l"(b));
    return d;
}
__device__ __forceinline__ u64 fadd2(u64 a, u64 b) {
    u64 d; asm("add.rn.f32x2 %0, %1, %2;" : "=l"(d) : "l"(a), "l"(b));
    return d;
}
__device__ __forceinline__ float fast_sigmoid(float x) {
    float e; asm("ex2.approx.f32 %0, %1;" : "=f"(e) : "f"(x * -1.4426950408889634f));
    float r; asm("rcp.approx.f32 %0, %1;" : "=f"(r) : "f"(e + 1.0f));
    return r;
}

__global__ __launch_bounds__(NTHR, 2)
void lstm2_kernel(const float* __restrict__ input,   // (B, T, 1)
                  const float* __restrict__ W_ih,    // (4H, 1)
                  const float* __restrict__ W_hh,    // (4H, H)
                  const float* __restrict__ b_ih,    // (4H)
                  const float* __restrict__ b_hh,    // (4H)
                  const float* __restrict__ W_fc,    // (1, H)
                  const float* __restrict__ b_fc,    // (1)
                  float* __restrict__ out)           // (B, T, 1)
{
    __shared__ __align__(16) float2 xsh[SEQLEN];     // x pairs, preloaded
    __shared__ __align__(16) float2 ysh[SEQLEN];     // y pairs, flushed at end
    __shared__ __align__(16) float2 hsh[2][HP];      // h pairs, double-buffered
    __shared__ __align__(16) float2 wfcsh[HP];       // (wfc, wfc) pairs

    const int tid = threadIdx.x;
    const int b0  = blockIdx.x * 2;

    // ---- one-time init ----
    for (int idx = tid; idx < SEQLEN; idx += NTHR)
        xsh[idx] = make_float2(input[b0 * SEQLEN + idx],
                               input[(b0 + 1) * SEQLEN + idx]);
    if (tid < 2 * HP) ((float2*)hsh)[tid] = make_float2(0.0f, 0.0f);
    if (tid < HP) {
        float w = (tid < HID) ? W_fc[tid] : 0.0f;
        wfcsh[tid] = make_float2(w, w);
    }

    const int gid  = tid & 3;            // gate: 0=i 1=f 2=g 3=o
    const int j    = tid >> 2;           // hidden unit 0..50
    const int grow = gid * HID + j;      // row in (4H, H)

    // gate row weights in registers, packed (w, w)
    u64 wpk[HP];
    #pragma unroll
    for (int k = 0; k < HID; k++) {
        float w = W_hh[grow * HID + k];
        wpk[k] = pk2(w, w);
    }
    wpk[HID] = 0ull;

    const float bb = b_ih[grow] + b_hh[grow];
    const u64 biaspk = pk2(bb, bb);
    const float wv = W_ih[grow];
    const u64 wihpk = pk2(wv, wv);
    const float bfc = b_fc[0];

    // divergence-free activation: act = mm * sigmoid(ks * a) + ba
    const float ks = (gid == 2) ? 2.0f : 1.0f;
    const float mm = (gid == 2) ? 2.0f : 1.0f;
    const float ba = (gid == 2) ? -1.0f : 0.0f;

    const unsigned lane = (unsigned)tid & 31u;
    const unsigned grpmask = 0xFu << (lane & 28u);   // my 4-lane gate group

    u64 c = 0ull;   // cell state pair (redundant across the 4 gate lanes)

    __syncthreads();

    for (int t = 0; t < SEQLEN; t++) {
        const u64* __restrict__ hb = (const u64*)hsh[t & 1];

        float2 xv = xsh[t];
        u64 a0 = ffma2(pk2(xv.x, xv.y), wihpk, biaspk);
        u64 a1 = 0ull, a2 = 0ull, a3 = 0ull;

        #pragma unroll
        for (int kk = 0; kk < HP; kk += 4) {
            ulonglong2 h0 = *(const ulonglong2*)(hb + kk);       // broadcast LDS.128
            ulonglong2 h1 = *(const ulonglong2*)(hb + kk + 2);
            a0 = ffma2(wpk[kk],     h0.x, a0);
            a1 = ffma2(wpk[kk + 1], h0.y, a1);
            a2 = ffma2(wpk[kk + 2], h1.x, a2);
            a3 = ffma2(wpk[kk + 3], h1.y, a3);
        }
        u64 a = fadd2(fadd2(a0, a1), fadd2(a2, a3));

        // activation on both f32 lanes
        float alo, ahi; upk2(a, alo, ahi);
        float slo = fast_sigmoid(ks * alo);
        float shi = fast_sigmoid(ks * ahi);
        u64 act = pk2(fmaf(mm, slo, ba), fmaf(mm, shi, ba));

        // 4-lane allgather of activated gates (u64 = 2x SHFL each)
        u64 v0 = act;
        u64 v1 = __shfl_xor_sync(grpmask, v0, 1, 32);
        u64 v2 = __shfl_xor_sync(grpmask, v0, 2, 32);
        u64 v3 = __shfl_xor_sync(grpmask, v1, 2, 32);
        // vX carries gate (gid ^ X); pick absolute gates:
        u64 iv = (gid == 0) ? v0 : (gid == 1) ? v1 : (gid == 2) ? v2 : v3;
        u64 fv = (gid == 0) ? v1 : (gid == 1) ? v0 : (gid == 2) ? v3 : v2;
        u64 gv = (gid == 0) ? v2 : (gid == 1) ? v3 : (gid == 2) ? v0 : v1;
        u64 ov = (gid == 0) ? v3 : (gid == 1) ? v2 : (gid == 2) ? v1 : v0;

        c = ffma2(fv, c, fmul2(iv, gv));
        float clo, chi; upk2(c, clo, chi);
        float tlo = fmaf(2.0f, fast_sigmoid(2.0f * clo), -1.0f);
        float thi = fmaf(2.0f, fast_sigmoid(2.0f * chi), -1.0f);
        u64 hn = fmul2(ov, pk2(tlo, thi));

        if (gid == 0) ((u64*)hsh[(t + 1) & 1])[j] = hn;
        __syncthreads();

        // y_t = h . wfc + bfc, split over lanes 0..3 (13 pairs each)
        if (tid < 4) {
            const u64* __restrict__ hv = (const u64*)hsh[(t + 1) & 1];
            const u64* __restrict__ wf = (const u64*)wfcsh;
            const int base = tid * 13;
            u64 s0 = 0ull, s1 = 0ull;
            #pragma unroll
            for (int q = 0; q < 12; q += 2) {
                s0 = ffma2(hv[base + q],     wf[base + q],     s0);
                s1 = ffma2(hv[base + q + 1], wf[base + q + 1], s1);
            }
            s0 = ffma2(hv[base + 12], wf[base + 12], s0);
            u64 s = fadd2(s0, s1);
            s = fadd2(s, __shfl_xor_sync(0xFu, s, 1, 32));
            s = fadd2(s, __shfl_xor_sync(0xFu, s, 2, 32));
            if (tid == 0) {
                float ylo, yhi; upk2(s, ylo, yhi);
                ysh[t] = make_float2(ylo + bfc, yhi + bfc);
            }
        }
        // next iteration writes buffer (t&1); ysh[t] slot never re-read.
    }

    __syncthreads();
    for (int idx = tid; idx < SEQLEN; idx += NTHR) {
        float2 y = ysh[idx];
        out[b0 * SEQLEN + idx]       = y.x;
        out[(b0 + 1) * SEQLEN + idx] = y.y;
    }
}

extern "C" void kernel_launch(void* const* d_in, const int* in_sizes, int n_in,
                              void* d_out, int out_size) {
    const float* input = (const float*)d_in[0];
    const float* W_ih  = (const float*)d_in[1];
    const float* W_hh  = (const float*)d_in[2];
    const float* b_ih  = (const float*)d_in[3];
    const float* b_hh  = (const float*)d_in[4];
    const float* W_fc  = (const float*)d_in[5];
    const float* b_fc  = (const float*)d_in[6];
    // d_in[7] = future (0) — ignored.
    float* out = (float*)d_out;

    lstm2_kernel<<<BATCH / 2, NTHR>>>(input, W_ih, W_hh, b_ih, b_hh,
                                      W_fc, b_fc, out);
}

// round 5
// speedup vs baseline: 1.3121x; 1.3121x over previous
#include <cuda_runtime.h>

// LSTM B=4096, T=999, I=1, H=51, O=1, future=0.
//
// CTA = 4 batch rows, 204 threads. Horizontal f32x2: each thread owns ONE
// gate row r; its 51 weights are packed as 26 (w_2k, w_2k+1) u64 register
// pairs (52 regs — same as scalar, unlike the batch-paired R3 scheme that
// duplicated weights). Batches are 4 independent f32x2 accumulators.
// h lives in SMEM as (h_2k, h_2k+1) pairs x 4 batches -> phase-1 loads are
// fully uniform (warp broadcast).
//
// Warp-local gate combine: warp w owns units [8w, 8w+8) (warp 6: 48..50),
// both the 4 gate rows AND the (unit,batch) combine slots -> gate exchange
// needs only __syncwarp. ONE __syncthreads per step (publishes h).
// FC output computed by threads tid<4 one step late, off the critical path.

#define HID    51
#define KP     26          // k-pairs (51 -> 26, last hi lane padded 0)
#define SEQLEN 999
#define NTHR   204
#define BATCH  4096
#define BT     4

typedef unsigned long long u64;

__device__ __forceinline__ u64 pk2(float lo, float hi) {
    u64 r;
    asm("mov.b64 %0, {%1, %2};"
        : "=l"(r) : "r"(__float_as_uint(lo)), "r"(__float_as_uint(hi)));
    return r;
}
__device__ __forceinline__ void upk2(u64 v, float& lo, float& hi) {
    unsigned a, b;
    asm("mov.b64 {%0, %1}, %2;" : "=r"(a), "=r"(b) : "l"(v));
    lo = __uint_as_float(a); hi = __uint_as_float(b);
}
__device__ __forceinline__ u64 ffma2(u64 a, u64 b, u64 c) {
    u64 d; asm("fma.rn.f32x2 %0, %1, %2, %3;" : "=l"(d) : "l"(a), "l"(b), "l"(c));
    return d;
}
__device__ __forceinline__ float fast_sig_scaled(float a, float kl2) {
    // sigmoid(ks*a) with kl2 = -ks*log2(e):  1/(1+2^(a*kl2))
    float e; asm("ex2.approx.f32 %0, %1;" : "=f"(e) : "f"(a * kl2));
    float r; asm("rcp.approx.f32 %0, %1;" : "=f"(r) : "f"(e + 1.0f));
    return r;
}

__global__ __launch_bounds__(NTHR, 2)
void lstm4_kernel(const float* __restrict__ input,   // (B, T, 1)
                  const float* __restrict__ W_ih,    // (4H, 1)
                  const float* __restrict__ W_hh,    // (4H, H)
                  const float* __restrict__ b_ih,    // (4H)
                  const float* __restrict__ b_hh,    // (4H)
                  const float* __restrict__ W_fc,    // (1, H)
                  const float* __restrict__ b_fc,    // (1)
                  float* __restrict__ out)           // (B, T, 1)
{
    __shared__ __align__(16) float4 xsh[SEQLEN];          // x of 4 batches per t
    __shared__ __align__(16) float  gact[4 * HID][BT];    // activated gates
    __shared__ __align__(16) u64    hsh[2][KP][BT];       // (h_2k,h_2k+1) pairs
    __shared__ __align__(16) u64    wfc2[KP];             // (wfc_2k, wfc_2k+1)

    const int tid = threadIdx.x;
    const int b0  = blockIdx.x * BT;

    // ---- one-time init ----
    #pragma unroll
    for (int b = 0; b < BT; b++)
        for (int idx = tid; idx < SEQLEN; idx += NTHR)
            ((float*)xsh)[idx * 4 + b] = input[(b0 + b) * SEQLEN + idx];

    for (int idx = tid; idx < 2 * KP * BT; idx += NTHR)
        ((u64*)hsh)[idx] = 0ull;                       // h0 = 0 (+ pad lanes)
    if (tid < KP)
        wfc2[tid] = pk2(W_fc[2 * tid],
                        (2 * tid + 1 < HID) ? W_fc[2 * tid + 1] : 0.0f);

    // warp-local role assignment
    const int w     = tid >> 5;
    const int lane  = tid & 31;
    const int wbase = (w < 6) ? 8 * w : 48;            // first unit of warp
    const int nu    = (w < 6) ? 8 : 3;                 // units in warp
    const unsigned wmask = (w < 6) ? 0xFFFFFFFFu : 0x00000FFFu;

    // phase-1 role: gate g, local unit jj -> row
    const int g   = lane / nu;                         // loop-invariant divide
    const int jj  = lane - g * nu;
    const int row = g * HID + wbase + jj;

    // phase-2 role: unit j2, batch b2
    const int j2  = wbase + (lane >> 2);
    const int b2  = lane & 3;

    // row weights, horizontally packed (w_2k, w_2k+1)
    u64 wpk[KP];
    #pragma unroll
    for (int kp = 0; kp < KP; kp++) {
        float wl = W_hh[row * HID + 2 * kp];
        float wh = (2 * kp + 1 < HID) ? W_hh[row * HID + 2 * kp + 1] : 0.0f;
        wpk[kp] = pk2(wl, wh);
    }
    const float bias = b_ih[row] + b_hh[row];
    const float wih  = W_ih[row];
    const float bfc  = b_fc[0];

    // activation: act = mm * sigmoid(ks*a) + ba  (g: tanh = 2*sig(2a)-1)
    const float kl2 = (g == 2) ? -2.8853900817779268f : -1.4426950408889634f;
    const float mm  = (g == 2) ? 2.0f : 1.0f;
    const float ba  = (g == 2) ? -1.0f : 0.0f;

    float c = 0.0f;                                    // cell state (j2, b2)

    __syncthreads();

    #pragma unroll 1
    for (int t = 0; t < SEQLEN; t++) {
        // ---- deferred FC output for step t-1 (reads the stable buffer) ----
        if (t > 0 && tid < BT) {
            const u64* __restrict__ hv = &hsh[t & 1][0][0];
            u64 s0 = 0ull, s1 = 0ull;
            #pragma unroll
            for (int kp = 0; kp < KP; kp += 2) {
                s0 = ffma2(hv[kp * 4 + tid],       wfc2[kp],     s0);
                s1 = ffma2(hv[(kp + 1) * 4 + tid], wfc2[kp + 1], s1);
            }
            float a, b, cc, d;
            upk2(s0, a, b); upk2(s1, cc, d);
            out[(b0 + tid) * SEQLEN + (t - 1)] = (a + b) + (cc + d) + bfc;
        }

        // ---- phase 1: gate-row preactivations (h reads = uniform broadcast)
        const u64* __restrict__ hb = &hsh[t & 1][0][0];
        u64 acc0 = 0ull, acc1 = 0ull, acc2 = 0ull, acc3 = 0ull;
        #pragma unroll
        for (int kp = 0; kp < KP; kp++) {
            ulonglong2 p01 = *(const ulonglong2*)(hb + kp * 4);
            ulonglong2 p23 = *(const ulonglong2*)(hb + kp * 4 + 2);
            acc0 = ffma2(wpk[kp], p01.x, acc0);
            acc1 = ffma2(wpk[kp], p01.y, acc1);
            acc2 = ffma2(wpk[kp], p23.x, acc2);
            acc3 = ffma2(wpk[kp], p23.y, acc3);
        }
        const float4 xv = xsh[t];
        float l0, h0, l1, h1, l2, h2, l3, h3;
        upk2(acc0, l0, h0); upk2(acc1, l1, h1);
        upk2(acc2, l2, h2); upk2(acc3, l3, h3);
        float a0 = (l0 + h0) + fmaf(xv.x, wih, bias);
        float a1 = (l1 + h1) + fmaf(xv.y, wih, bias);
        float a2 = (l2 + h2) + fmaf(xv.z, wih, bias);
        float a3 = (l3 + h3) + fmaf(xv.w, wih, bias);

        float4 av;
        av.x = fmaf(mm, fast_sig_scaled(a0, kl2), ba);
        av.y = fmaf(mm, fast_sig_scaled(a1, kl2), ba);
        av.z = fmaf(mm, fast_sig_scaled(a2, kl2), ba);
        av.w = fmaf(mm, fast_sig_scaled(a3, kl2), ba);
        *(float4*)&gact[row][0] = av;

        __syncwarp(wmask);

        // ---- phase 2: cell/h update for (unit j2, batch b2) ----
        const float ig = gact[          j2][b2];
        const float fg = gact[    HID + j2][b2];
        const float gg = gact[2 * HID + j2][b2];
        const float og = gact[3 * HID + j2][b2];
        c = fmaf(fg, c, ig * gg);
        // tanh(c) = 2*sigmoid(2c) - 1
        float e; asm("ex2.approx.f32 %0, %1;"
                     : "=f"(e) : "f"(c * -2.8853900817779268f));
        float r; asm("rcp.approx.f32 %0, %1;" : "=f"(r) : "f"(e + 1.0f));
        const float hn = og * fmaf(2.0f, r, -1.0f);

        // publish h into pair layout: hsh[nxt][j2>>1][b2] lane (j2&1)
        ((float*)&hsh[(t + 1) & 1][j2 >> 1][b2])[j2 & 1] = hn;

        __syncthreads();
    }

    // final FC output for t = SEQLEN-1
    if (tid < BT) {
        const u64* __restrict__ hv = &hsh[SEQLEN & 1][0][0];
        u64 s0 = 0ull, s1 = 0ull;
        #pragma unroll
        for (int kp = 0; kp < KP; kp += 2) {
            s0 = ffma2(hv[kp * 4 + tid],       wfc2[kp],     s0);
            s1 = ffma2(hv[(kp + 1) * 4 + tid], wfc2[kp + 1], s1);
        }
        float a, b, cc, d;
        upk2(s0, a, b); upk2(s1, cc, d);
        out[(b0 + tid) * SEQLEN + (SEQLEN - 1)] = (a + b) + (cc + d) + bfc;
    }
}

extern "C" void kernel_launch(void* const* d_in, const int* in_sizes, int n_in,
                              void* d_out, int out_size) {
    const float* input = (const float*)d_in[0];
    const float* W_ih  = (const float*)d_in[1];
    const float* W_hh  = (const float*)d_in[2];
    const float* b_ih  = (const float*)d_in[3];
    const float* b_hh  = (const float*)d_in[4];
    const float* W_fc  = (const float*)d_in[5];
    const float* b_fc  = (const float*)d_in[6];
    // d_in[7] = future (0) — ignored.
    float* out = (float*)d_out;

    lstm4_kernel<<<BATCH / BT, NTHR>>>(input, W_ih, W_hh, b_ih, b_hh,
                                       W_fc, b_fc, out);
}

// round 6
// speedup vs baseline: 1.8571x; 1.4153x over previous
#include <cuda_runtime.h>

// LSTM B=4096, T=999, I=1, H=51, O=1, future=0.
//
// rows-per-thread=2 design: thread pair (A,B) per hidden unit j, BT=4
// batches per CTA, 128 threads (102 active + 4 FC lanes + pad).
//   A (even lane) owns gate rows i (j) and g (2H+j)
//   B (odd  lane) owns gate rows f (H+j) and o (3H+j), plus cell state c
// Weights horizontal-f32x2-packed in registers (102 floats -> 52 u64).
// Per step/thread: 52 LDS.128 (h pairs, 4 batches) vs 208 FFMA2 (ratio 4,
// 2x R4 -> halves the L1 wavefront pressure that bound R2/R4).
// Gate combine: A sends sig(i)*tanh(g) to B via one shfl_xor(1) per
// batch-pair. B updates c/h, publishes h. ONE __syncthreads per step.
// FC output handled by 4 pad lanes, deferred one step (off critical path).

#define HID    51
#define KP     26
#define SEQLEN 999
#define BT     4
#define NTHR   128
#define BATCH  4096

typedef unsigned long long u64;

__device__ __forceinline__ u64 pk2(float lo, float hi) {
    u64 r;
    asm("mov.b64 %0, {%1, %2};"
        : "=l"(r) : "r"(__float_as_uint(lo)), "r"(__float_as_uint(hi)));
    return r;
}
__device__ __forceinline__ void upk2(u64 v, float& lo, float& hi) {
    unsigned a, b;
    asm("mov.b64 {%0, %1}, %2;" : "=r"(a), "=r"(b) : "l"(v));
    lo = __uint_as_float(a); hi = __uint_as_float(b);
}
__device__ __forceinline__ u64 ffma2(u64 a, u64 b, u64 c) {
    u64 d; asm("fma.rn.f32x2 %0, %1, %2, %3;" : "=l"(d) : "l"(a), "l"(b), "l"(c));
    return d;
}
__device__ __forceinline__ float fast_sig_scaled(float a, float kl2) {
    // sigmoid(ks*a), kl2 = -ks*log2(e)
    float e; asm("ex2.approx.f32 %0, %1;" : "=f"(e) : "f"(a * kl2));
    float r; asm("rcp.approx.f32 %0, %1;" : "=f"(r) : "f"(e + 1.0f));
    return r;
}
__device__ __forceinline__ float fast_tanh(float x) {
    float e; asm("ex2.approx.f32 %0, %1;"
                 : "=f"(e) : "f"(x * -2.8853900817779268f));
    float r; asm("rcp.approx.f32 %0, %1;" : "=f"(r) : "f"(e + 1.0f));
    return fmaf(2.0f, r, -1.0f);
}

__global__ __launch_bounds__(NTHR, 3)
void lstm5_kernel(const float* __restrict__ input,   // (B, T, 1)
                  const float* __restrict__ W_ih,    // (4H, 1)
                  const float* __restrict__ W_hh,    // (4H, H)
                  const float* __restrict__ b_ih,    // (4H)
                  const float* __restrict__ b_hh,    // (4H)
                  const float* __restrict__ W_fc,    // (1, H)
                  const float* __restrict__ b_fc,    // (1)
                  float* __restrict__ out)           // (B, T, 1)
{
    __shared__ __align__(16) float4 xsh[SEQLEN];        // x of 4 batches
    __shared__ __align__(16) u64    hsh[2][KP][BT];     // (h_2k,h_2k+1) pairs
    __shared__ __align__(16) u64    wfc2[KP];

    const int tid = threadIdx.x;
    const int b0  = blockIdx.x * BT;

    // ---- one-time init ----
    #pragma unroll
    for (int b = 0; b < BT; b++)
        for (int idx = tid; idx < SEQLEN; idx += NTHR)
            ((float*)xsh)[idx * 4 + b] = input[(b0 + b) * SEQLEN + idx];
    for (int idx = tid; idx < 2 * KP * BT; idx += NTHR)
        ((u64*)hsh)[idx] = 0ull;
    if (tid < KP)
        wfc2[tid] = pk2(W_fc[2 * tid],
                        (2 * tid + 1 < HID) ? W_fc[2 * tid + 1] : 0.0f);

    const int j      = tid >> 1;         // unit (valid < 51)
    const int p      = tid & 1;          // 0 = A(i,g), 1 = B(f,o)
    const bool active = (tid < 2 * HID); // tid < 102
    const bool fcRole = (tid >= 104 && tid < 108);
    const int  fb     = tid - 104;
    // warp 3 holds only 6 active lanes (tid 96..101)
    const unsigned wmask = (tid >= 96) ? 0x3Fu : 0xFFFFFFFFu;

    const int row1 = p * HID + j;        // i or f
    const int row2 = (2 + p) * HID + j;  // g or o

    u64 w1[KP], w2[KP];
    float bias1 = 0.f, bias2 = 0.f, wih1 = 0.f, wih2 = 0.f;
    if (active) {
        #pragma unroll
        for (int kp = 0; kp < KP; kp++) {
            int k0 = 2 * kp, k1 = 2 * kp + 1;
            float a0 = W_hh[row1 * HID + k0];
            float a1 = (k1 < HID) ? W_hh[row1 * HID + k1] : 0.0f;
            float c0 = W_hh[row2 * HID + k0];
            float c1 = (k1 < HID) ? W_hh[row2 * HID + k1] : 0.0f;
            w1[kp] = pk2(a0, a1);
            w2[kp] = pk2(c0, c1);
        }
        bias1 = b_ih[row1] + b_hh[row1];
        bias2 = b_ih[row2] + b_hh[row2];
        wih1  = W_ih[row1];
        wih2  = W_ih[row2];
    } else {
        #pragma unroll
        for (int kp = 0; kp < KP; kp++) { w1[kp] = 0ull; w2[kp] = 0ull; }
    }
    const float bfc = b_fc[0];

    // row1 is always sigmoid (i or f); row2: tanh for A (g), sigmoid for B (o)
    const float kl2_2 = (p == 0) ? -2.8853900817779268f : -1.4426950408889634f;
    const float mm2   = (p == 0) ? 2.0f : 1.0f;
    const float ba2   = (p == 0) ? -1.0f : 0.0f;
    const float KL2   = -1.4426950408889634f;

    u64 c01 = 0ull, c23 = 0ull;          // cell state pairs (B lanes only)

    __syncthreads();

    #pragma unroll 1
    for (int t = 0; t < SEQLEN; t++) {
        const u64* __restrict__ hb = &hsh[t & 1][0][0];

        // ---- deferred FC for step t-1 (pad lanes; stable buffer) ----
        if (fcRole && t > 0) {
            u64 s0 = 0ull, s1 = 0ull;
            #pragma unroll
            for (int kp = 0; kp < KP; kp += 2) {
                s0 = ffma2(hb[kp * 4 + fb],       wfc2[kp],     s0);
                s1 = ffma2(hb[(kp + 1) * 4 + fb], wfc2[kp + 1], s1);
            }
            float aa, bb, cc, dd;
            upk2(s0, aa, bb); upk2(s1, cc, dd);
            out[(b0 + fb) * SEQLEN + (t - 1)] = (aa + bb) + (cc + dd) + bfc;
        }

        if (active) {
            // ---- phase 1: two gate-row dots for 4 batches ----
            u64 a1b0 = 0ull, a1b1 = 0ull, a1b2 = 0ull, a1b3 = 0ull;
            u64 a2b0 = 0ull, a2b1 = 0ull, a2b2 = 0ull, a2b3 = 0ull;
            #pragma unroll
            for (int kp = 0; kp < KP; kp++) {
                ulonglong2 q01 = *(const ulonglong2*)(hb + kp * 4);
                ulonglong2 q23 = *(const ulonglong2*)(hb + kp * 4 + 2);
                a1b0 = ffma2(w1[kp], q01.x, a1b0);
                a1b1 = ffma2(w1[kp], q01.y, a1b1);
                a1b2 = ffma2(w1[kp], q23.x, a1b2);
                a1b3 = ffma2(w1[kp], q23.y, a1b3);
                a2b0 = ffma2(w2[kp], q01.x, a2b0);
                a2b1 = ffma2(w2[kp], q01.y, a2b1);
                a2b2 = ffma2(w2[kp], q23.x, a2b2);
                a2b3 = ffma2(w2[kp], q23.y, a2b3);
            }
            const float4 xv = xsh[t];
            float g1[BT], g2[BT];
            {
                float lo, hi;
                upk2(a1b0, lo, hi); g1[0] = (lo + hi) + fmaf(xv.x, wih1, bias1);
                upk2(a1b1, lo, hi); g1[1] = (lo + hi) + fmaf(xv.y, wih1, bias1);
                upk2(a1b2, lo, hi); g1[2] = (lo + hi) + fmaf(xv.z, wih1, bias1);
                upk2(a1b3, lo, hi); g1[3] = (lo + hi) + fmaf(xv.w, wih1, bias1);
                upk2(a2b0, lo, hi); g2[0] = (lo + hi) + fmaf(xv.x, wih2, bias2);
                upk2(a2b1, lo, hi); g2[1] = (lo + hi) + fmaf(xv.y, wih2, bias2);
                upk2(a2b2, lo, hi); g2[2] = (lo + hi) + fmaf(xv.z, wih2, bias2);
                upk2(a2b3, lo, hi); g2[3] = (lo + hi) + fmaf(xv.w, wih2, bias2);
            }
            float act1[BT], act2[BT], prod[BT];
            #pragma unroll
            for (int b = 0; b < BT; b++) {
                act1[b] = fast_sig_scaled(g1[b], KL2);                 // sig(i|f)
                act2[b] = fmaf(mm2, fast_sig_scaled(g2[b], kl2_2), ba2);
                prod[b] = act1[b] * act2[b];   // A: sig(i)*tanh(g)
            }

            // ---- exchange A -> B (xor 1) ----
            u64 p01 = pk2(prod[0], prod[1]);
            u64 p23 = pk2(prod[2], prod[3]);
            u64 r01 = __shfl_xor_sync(wmask, p01, 1, 32);
            u64 r23 = __shfl_xor_sync(wmask, p23, 1, 32);

            // ---- phase 2: B updates c, h and publishes ----
            if (p == 1) {
                u64 f01 = pk2(act1[0], act1[1]);
                u64 f23 = pk2(act1[2], act1[3]);
                c01 = ffma2(f01, c01, r01);
                c23 = ffma2(f23, c23, r23);
                float c0, c1, c2, c3;
                upk2(c01, c0, c1); upk2(c23, c2, c3);
                float h0 = act2[0] * fast_tanh(c0);
                float h1 = act2[1] * fast_tanh(c1);
                float h2 = act2[2] * fast_tanh(c2);
                float h3 = act2[3] * fast_tanh(c3);
                float* hn = (float*)&hsh[(t + 1) & 1][j >> 1][0] + (j & 1);
                hn[0] = h0; hn[2] = h1; hn[4] = h2; hn[6] = h3;
            }
        }
        __syncthreads();
    }

    // final FC for t = SEQLEN-1
    if (fcRole) {
        const u64* __restrict__ hv = &hsh[SEQLEN & 1][0][0];
        u64 s0 = 0ull, s1 = 0ull;
        #pragma unroll
        for (int kp = 0; kp < KP; kp += 2) {
            s0 = ffma2(hv[kp * 4 + fb],       wfc2[kp],     s0);
            s1 = ffma2(hv[(kp + 1) * 4 + fb], wfc2[kp + 1], s1);
        }
        float aa, bb, cc, dd;
        upk2(s0, aa, bb); upk2(s1, cc, dd);
        out[(b0 + fb) * SEQLEN + (SEQLEN - 1)] = (aa + bb) + (cc + dd) + bfc;
    }
}

extern "C" void kernel_launch(void* const* d_in, const int* in_sizes, int n_in,
                              void* d_out, int out_size) {
    const float* input = (const float*)d_in[0];
    const float* W_ih  = (const float*)d_in[1];
    const float* W_hh  = (const float*)d_in[2];
    const float* b_ih  = (const float*)d_in[3];
    const float* b_hh  = (const float*)d_in[4];
    const float* W_fc  = (const float*)d_in[5];
    const float* b_fc  = (const float*)d_in[6];
    // d_in[7] = future (0) — ignored.
    float* out = (float*)d_out;

    lstm5_kernel<<<BATCH / BT, NTHR>>>(input, W_ih, W_hh, b_ih, b_hh,
                                       W_fc, b_fc, out);
}